// round 1
// baseline (speedup 1.0000x reference)
#include <cuda_runtime.h>
#include <math.h>

#define N_ROWS   131072
#define IN_D     12
#define HID      256
#define NL       10
#define OUT_D    3
#define TM       64            // rows per CTA
#define KC       32            // k-chunk of W staged in smem
#define NCHUNK   (HID / KC)    // 8
#define NTHREADS 256

// act: 0=sin 1=cos 2=gauss 3=tanh
__device__ __forceinline__ float actf(float v, int mode) {
    switch (mode) {
        case 0:  return sinf(v);
        case 1:  return cosf(v);
        case 2:  return expf(-v * v);
        default: return tanhf(v);
    }
}

__global__ void __launch_bounds__(NTHREADS, 1)
cppn_kernel(const float* __restrict__ x,
            const float* __restrict__ W0,
            const float* __restrict__ b0,
            const float* __restrict__ Ws,
            const float* __restrict__ bs,
            const float* __restrict__ Wout,
            const float* __restrict__ bout,
            float* __restrict__ out)
{
    extern __shared__ float sm[];
    float* hbuf0 = sm;                      // [HID][TM] activations (transposed: [k][m])
    float* hbuf1 = sm + HID * TM;           // [HID][TM]
    float* wbA   = sm + 2 * HID * TM;       // [KC][HID] weight stage buffer A
    float* wbB   = wbA + KC * HID;          // [KC][HID] weight stage buffer B

    const int tid  = threadIdx.x;
    const int row0 = blockIdx.x * TM;
    const int m0   = (tid & 7) * 8;         // 8 m-rows per thread
    const int n0   = (tid >> 3) * 8;        // 8 n-cols per thread

    float acc[8][8];

    // ======================= layer 0: x(12) -> 256, sin =======================
    {
        // stage W0 (12x256 = 768 float4) into wbA; x tile transposed into wbB as xs[k][m]
        const float4* W0v = (const float4*)W0;
        float4* wa = (float4*)wbA;
        #pragma unroll
        for (int idx = tid; idx < IN_D * HID / 4; idx += NTHREADS) wa[idx] = W0v[idx];
        for (int idx = tid; idx < TM * IN_D; idx += NTHREADS) {
            int m = idx / IN_D, k = idx % IN_D;
            wbB[k * TM + m] = x[(size_t)(row0 + m) * IN_D + k];
        }
        __syncthreads();

        #pragma unroll
        for (int i = 0; i < 8; i++)
            #pragma unroll
            for (int j = 0; j < 8; j++) acc[i][j] = 0.0f;

        #pragma unroll
        for (int k = 0; k < IN_D; k++) {
            const float* hp = wbB + k * TM;
            const float* wp = wbA + k * HID;
            float4 a0 = *(const float4*)(hp + m0);
            float4 a1 = *(const float4*)(hp + m0 + 4);
            float4 w0 = *(const float4*)(wp + n0);
            float4 w1 = *(const float4*)(wp + n0 + 4);
            float a[8] = {a0.x,a0.y,a0.z,a0.w,a1.x,a1.y,a1.z,a1.w};
            float w[8] = {w0.x,w0.y,w0.z,w0.w,w1.x,w1.y,w1.z,w1.w};
            #pragma unroll
            for (int i = 0; i < 8; i++)
                #pragma unroll
                for (int j = 0; j < 8; j++)
                    acc[i][j] = fmaf(a[i], w[j], acc[i][j]);
        }

        // bias + sin -> hbuf0 (transposed store h[n][m])
        float4 bv0 = *(const float4*)(b0 + n0);
        float4 bv1 = *(const float4*)(b0 + n0 + 4);
        float bb[8] = {bv0.x,bv0.y,bv0.z,bv0.w,bv1.x,bv1.y,bv1.z,bv1.w};
        #pragma unroll
        for (int j = 0; j < 8; j++)
            #pragma unroll
            for (int i = 0; i < 8; i++)
                hbuf0[(n0 + j) * TM + m0 + i] = actf(acc[i][j] + bb[j], 0);
    }

    // ======================= hidden layers 1..9: 256 -> 256 ===================
    float* hc = hbuf0;
    float* hn = hbuf1;

    for (int layer = 1; layer < NL; layer++) {
        const float*  W    = Ws + (size_t)(layer - 1) * HID * HID;
        const float*  bias = bs + (layer - 1) * HID;
        const float4* Wv   = (const float4*)W;
        const int mode = layer & 3;

        __syncthreads();   // prior layer fully done before overwriting weight buffers

        #pragma unroll
        for (int i = 0; i < 8; i++)
            #pragma unroll
            for (int j = 0; j < 8; j++) acc[i][j] = 0.0f;

        // preload chunk 0 -> wbA, start chunk 1 -> regs
        float4 pf[8];
        {
            #pragma unroll
            for (int r = 0; r < 8; r++) pf[r] = Wv[r * 256 + tid];
            float4* wd = (float4*)wbA;
            #pragma unroll
            for (int r = 0; r < 8; r++) wd[r * 256 + tid] = pf[r];
            #pragma unroll
            for (int r = 0; r < 8; r++) pf[r] = Wv[2048 + r * 256 + tid];
        }
        __syncthreads();

        #pragma unroll 1
        for (int c = 0; c < NCHUNK; c++) {
            const float* Wbuf = (c & 1) ? wbB : wbA;
            const float* hrow = hc + c * KC * TM;

            #pragma unroll 4
            for (int kk = 0; kk < KC; kk++) {
                const float* hp = hrow + kk * TM;
                const float* wp = Wbuf + kk * HID;
                float4 a0 = *(const float4*)(hp + m0);
                float4 a1 = *(const float4*)(hp + m0 + 4);
                float4 w0 = *(const float4*)(wp + n0);
                float4 w1 = *(const float4*)(wp + n0 + 4);
                float a[8] = {a0.x,a0.y,a0.z,a0.w,a1.x,a1.y,a1.z,a1.w};
                float w[8] = {w0.x,w0.y,w0.z,w0.w,w1.x,w1.y,w1.z,w1.w};
                #pragma unroll
                for (int i = 0; i < 8; i++)
                    #pragma unroll
                    for (int j = 0; j < 8; j++)
                        acc[i][j] = fmaf(a[i], w[j], acc[i][j]);
            }

            if (c + 1 < NCHUNK) {
                __syncthreads();   // everyone done reading the buffer we overwrite
                float4* wd = (float4*)((c & 1) ? wbA : wbB);
                #pragma unroll
                for (int r = 0; r < 8; r++) wd[r * 256 + tid] = pf[r];
                if (c + 2 < NCHUNK) {
                    #pragma unroll
                    for (int r = 0; r < 8; r++)
                        pf[r] = Wv[(c + 2) * 2048 + r * 256 + tid];
                }
                __syncthreads();   // staged chunk visible
            }
        }

        // bias + act -> hn (transposed store)
        float4 bv0 = *(const float4*)(bias + n0);
        float4 bv1 = *(const float4*)(bias + n0 + 4);
        float bb[8] = {bv0.x,bv0.y,bv0.z,bv0.w,bv1.x,bv1.y,bv1.z,bv1.w};
        #pragma unroll
        for (int j = 0; j < 8; j++)
            #pragma unroll
            for (int i = 0; i < 8; i++)
                hn[(n0 + j) * TM + m0 + i] = actf(acc[i][j] + bb[j], mode);

        float* t = hc; hc = hn; hn = t;
    }

    // ======================= output layer: 256 -> 3, sigmoid ==================
    __syncthreads();
    if (tid < TM * OUT_D) {                 // 192 threads: one (row, col) each
        const int m = tid / OUT_D;
        const int j = tid % OUT_D;
        float s = bout[j];
        #pragma unroll 8
        for (int k = 0; k < HID; k++)
            s = fmaf(hc[k * TM + m], Wout[k * OUT_D + j], s);
        out[(size_t)(row0 + m) * OUT_D + j] = 1.0f / (1.0f + expf(-s));
    }
}

extern "C" void kernel_launch(void* const* d_in, const int* in_sizes, int n_in,
                              void* d_out, int out_size)
{
    const float* x    = (const float*)d_in[0];
    const float* W0   = (const float*)d_in[1];
    const float* b0   = (const float*)d_in[2];
    const float* Ws   = (const float*)d_in[3];
    const float* bs   = (const float*)d_in[4];
    const float* Wout = (const float*)d_in[5];
    const float* bout = (const float*)d_in[6];
    float* out = (float*)d_out;

    const int smem_bytes = (2 * HID * TM + 2 * KC * HID) * (int)sizeof(float); // 192 KB
    cudaFuncSetAttribute(cppn_kernel, cudaFuncAttributeMaxDynamicSharedMemorySize, smem_bytes);

    dim3 grid(N_ROWS / TM);   // 2048 CTAs
    dim3 block(NTHREADS);
    cppn_kernel<<<grid, block, smem_bytes>>>(x, W0, b0, Ws, bs, Wout, bout, out);
}